// round 4
// baseline (speedup 1.0000x reference)
#include <cuda_runtime.h>
#include <cuda_fp16.h>
#include <cstdint>
#include <cstddef>

// Problem constants
#define BB   64
#define TT   12
#define HH   6400
#define G3   19200            // 3*H
#define IN0P 256              // layer-0 input size padded 200 -> 256
#define BH   (BB*HH)          // 409600
#define TBH  (TT*BB*HH)       // 4915200

// ---------------- device scratch (sanctioned: __device__ globals) -------------
__device__ __half g_Whh0[(size_t)G3*HH];
__device__ __half g_Wih1[(size_t)G3*HH];
__device__ __half g_Whh1[(size_t)G3*HH];
__device__ __half g_W0p [(size_t)G3*IN0P];
__device__ __half g_A0  [768*IN0P];
__device__ float  g_gi0 [(size_t)768*G3];
__device__ float  g_gi1 [(size_t)768*G3];
__device__ __half g_h0s [TBH];
__device__ float  g_gh  [(size_t)BB*G3];
__device__ float  g_h   [BH];
__device__ __half g_hh  [BH];
__device__ float  g_zf  [BH];
__device__ __half g_zh  [BH];

// ---------------- fp32 -> fp16 bulk convert -----------------------------------
__global__ void f2h_k(const float* __restrict__ s, __half* __restrict__ d, int n4)
{
    int i = blockIdx.x * blockDim.x + threadIdx.x;
    int str = gridDim.x * blockDim.x;
    for (; i < n4; i += str) {
        float4 v = ((const float4*)s)[i];
        __half2 h0 = __floats2half2_rn(v.x, v.y);
        __half2 h1 = __floats2half2_rn(v.z, v.w);
        uint2 o;
        o.x = *(uint32_t*)&h0;
        o.y = *(uint32_t*)&h1;
        ((uint2*)d)[i] = o;
    }
}

// layer-0 A: (B,T,200) -> padded (T*B, 256) fp16, row = t*64+b
__global__ void prep_a0_k(const float* __restrict__ x, __half* __restrict__ d)
{
    int idx = blockIdx.x * 256 + threadIdx.x;
    if (idx >= 768 * IN0P) return;
    int row = idx >> 8, c = idx & 255;
    int t = row >> 6, b = row & 63;
    float v = (c < 200) ? x[b * 2400 + t * 200 + c] : 0.f;
    d[idx] = __float2half_rn(v);
}

// W_ih0: (19200,200) -> padded (19200,256) fp16
__global__ void prep_w0_k(const float* __restrict__ w, __half* __restrict__ d)
{
    int idx = blockIdx.x * 256 + threadIdx.x;
    if (idx >= G3 * IN0P) return;
    int g = idx >> 8, c = idx & 255;
    float v = (c < 200) ? w[g * 200 + c] : 0.f;
    d[idx] = __float2half_rn(v);
}

__global__ void zero_k(float* zf, __half* zh)
{
    int idx = blockIdx.x * 256 + threadIdx.x;
    if (idx < BH) { zf[idx] = 0.f; zh[idx] = __float2half(0.f); }
}

// ---------------- generic fp16 tensor-core GEMM: C = A * W^T + bias -----------
// A: (M,K) fp16 row-major, W: (N,K) fp16 row-major (== col-major B operand),
// C: (M,N) fp32. CTA tile 64x128, 8 warps; warp = all 4 m16 tiles x 2 n8 tiles.
// A tile via cp.async double-buffer; W fragments LDG'd direct from global with
// one-iteration register prefetch (each W element loaded exactly once per CTA).
__device__ __forceinline__ void load_wfrag(uint32_t dst[2][4][2],
                                           const __half* w0, const __half* w1,
                                           int kk, int klane)
{
#pragma unroll
    for (int ks = 0; ks < 4; ks++) {
        int k0 = kk + ks * 16 + klane;
        dst[0][ks][0] = *(const uint32_t*)(w0 + k0);
        dst[0][ks][1] = *(const uint32_t*)(w0 + k0 + 8);
        dst[1][ks][0] = *(const uint32_t*)(w1 + k0);
        dst[1][ks][1] = *(const uint32_t*)(w1 + k0 + 8);
    }
}

__global__ __launch_bounds__(256, 2) void gemm_f16(
    const __half* __restrict__ A, const __half* __restrict__ W,
    const float* __restrict__ bias, float* __restrict__ C,
    int M, int N, int K)
{
    __shared__ __half sA[2][64][72];   // 64 rows x 64 cols, +8 pad (conflict-free ldmatrix)

    const int tid  = threadIdx.x;
    const int warp = tid >> 5;
    const int lane = tid & 31;
    const int mbase = blockIdx.y << 6;
    const int nbase = blockIdx.x << 7;

    const __half* Ab = A + (size_t)mbase * K;
    const int g0 = nbase + warp * 16 + (lane >> 2);
    const __half* w0 = W + (size_t)g0 * K;
    const __half* w1 = W + (size_t)(g0 + 8) * K;
    const int klane = (lane & 3) * 2;

    float acc[4][2][4];
#pragma unroll
    for (int a = 0; a < 4; a++)
#pragma unroll
        for (int b = 0; b < 2; b++)
#pragma unroll
            for (int c = 0; c < 4; c++) acc[a][b][c] = 0.f;

    // A-tile cooperative load mapping: 2 chunks of 16B per thread
    const int r0 = tid >> 3;              // rows 0..31 (chunk0), +32 (chunk1)
    const int c0 = (tid & 7) * 8;         // col groups of 8 halves

#define CPA(bufi, kk) do {                                                        \
        uint32_t d0 = (uint32_t)__cvta_generic_to_shared(&sA[bufi][r0][c0]);      \
        uint32_t d1 = (uint32_t)__cvta_generic_to_shared(&sA[bufi][r0+32][c0]);   \
        const __half* s0 = Ab + (size_t)r0 * K + (kk) + c0;                       \
        const __half* s1 = Ab + (size_t)(r0+32) * K + (kk) + c0;                  \
        asm volatile("cp.async.cg.shared.global [%0], [%1], 16;\n"                \
                     :: "r"(d0), "l"(s0));                                        \
        asm volatile("cp.async.cg.shared.global [%0], [%1], 16;\n"                \
                     :: "r"(d1), "l"(s1));                                        \
        asm volatile("cp.async.commit_group;\n" ::);                              \
    } while (0)

    uint32_t bw[2][4][2], bwn[2][4][2];

    CPA(0, 0);
    load_wfrag(bw, w0, w1, 0, klane);

    const int nk = K >> 6;
    int buf = 0;
    for (int it = 0; it < nk; ++it) {
        if (it + 1 < nk) {
            CPA(buf ^ 1, (it + 1) << 6);
            asm volatile("cp.async.wait_group 1;\n" ::: "memory");
        } else {
            asm volatile("cp.async.wait_group 0;\n" ::: "memory");
        }
        __syncthreads();

        if (it + 1 < nk) load_wfrag(bwn, w0, w1, (it + 1) << 6, klane);

#pragma unroll
        for (int ks = 0; ks < 4; ks++) {
            uint32_t a0[4], a1[4], a2[4], a3[4];
#pragma unroll
            for (int mt = 0; mt < 4; mt++) {
                uint32_t ad = (uint32_t)__cvta_generic_to_shared(
                    &sA[buf][mt * 16 + (lane & 15)][ks * 16 + ((lane >> 4) << 3)]);
                asm volatile(
                    "ldmatrix.sync.aligned.m8n8.x4.shared.b16 {%0,%1,%2,%3}, [%4];\n"
                    : "=r"(a0[mt]), "=r"(a1[mt]), "=r"(a2[mt]), "=r"(a3[mt])
                    : "r"(ad));
            }
#pragma unroll
            for (int mt = 0; mt < 4; mt++)
#pragma unroll
                for (int nt = 0; nt < 2; nt++) {
                    asm volatile(
                        "mma.sync.aligned.m16n8k16.row.col.f32.f16.f16.f32 "
                        "{%0,%1,%2,%3}, {%4,%5,%6,%7}, {%8,%9}, {%0,%1,%2,%3};\n"
                        : "+f"(acc[mt][nt][0]), "+f"(acc[mt][nt][1]),
                          "+f"(acc[mt][nt][2]), "+f"(acc[mt][nt][3])
                        : "r"(a0[mt]), "r"(a1[mt]), "r"(a2[mt]), "r"(a3[mt]),
                          "r"(bw[nt][ks][0]), "r"(bw[nt][ks][1]));
                }
        }
        __syncthreads();

        if (it + 1 < nk) {
#pragma unroll
            for (int nt = 0; nt < 2; nt++)
#pragma unroll
                for (int ks = 0; ks < 4; ks++) {
                    bw[nt][ks][0] = bwn[nt][ks][0];
                    bw[nt][ks][1] = bwn[nt][ks][1];
                }
        }
        buf ^= 1;
    }

    // epilogue: C[m][n] = acc + bias[n]
#pragma unroll
    for (int mt = 0; mt < 4; mt++) {
        int row = mbase + mt * 16 + (lane >> 2);
#pragma unroll
        for (int nt = 0; nt < 2; nt++) {
            int col = nbase + warp * 16 + nt * 8 + klane;
            float bv0 = bias[col], bv1 = bias[col + 1];
            float2 v0 = make_float2(acc[mt][nt][0] + bv0, acc[mt][nt][1] + bv1);
            float2 v1 = make_float2(acc[mt][nt][2] + bv0, acc[mt][nt][3] + bv1);
            *(float2*)&C[(size_t)row * N + col]       = v0;
            *(float2*)&C[(size_t)(row + 8) * N + col] = v1;
        }
    }
#undef CPA
}

// ---------------- fused GRU gate pointwise ------------------------------------
// r = sig(gi_r+gh_r); z = sig(gi_z+gh_z); n = tanh(gi_n + r*gh_n)
// h_new = n + z*(h_prev - n)
__global__ void gate_k(const float* __restrict__ gi, const float* __restrict__ gh,
                       const float* __restrict__ hp, float* __restrict__ ho,
                       __half* __restrict__ hoh, float* __restrict__ extra)
{
    int idx = blockIdx.x * 256 + threadIdx.x;
    if (idx >= BH) return;
    int b = idx / HH, j = idx - b * HH;
    const float* gib = gi + (size_t)b * G3;
    const float* ghb = gh + (size_t)b * G3;
    float xr = gib[j]          + ghb[j];
    float xz = gib[j + HH]     + ghb[j + HH];
    float r  = 1.f / (1.f + __expf(-xr));
    float z  = 1.f / (1.f + __expf(-xz));
    float n  = tanhf(gib[j + 2 * HH] + r * ghb[j + 2 * HH]);
    float hn = fmaf(z, hp[idx] - n, n);
    ho[idx]  = hn;
    hoh[idx] = __float2half_rn(hn);
    if (extra) extra[idx] = hn;
}

// ---------------- host orchestration ------------------------------------------
extern "C" void kernel_launch(void* const* d_in, const int* in_sizes, int n_in,
                              void* d_out, int out_size)
{
    const float* x    = (const float*)d_in[0];
    const float* Wih0 = (const float*)d_in[1];
    const float* Whh0 = (const float*)d_in[2];
    const float* bih0 = (const float*)d_in[3];
    const float* bhh0 = (const float*)d_in[4];
    const float* Wih1 = (const float*)d_in[5];
    const float* Whh1 = (const float*)d_in[6];
    const float* bih1 = (const float*)d_in[7];
    const float* bhh1 = (const float*)d_in[8];
    float* out = (float*)d_out;

    __half *pWhh0, *pWih1, *pWhh1, *pW0p, *pA0, *pH0s, *pHh, *pZh;
    float  *pGi0, *pGi1, *pGh, *pH, *pZf;
    cudaGetSymbolAddress((void**)&pWhh0, g_Whh0);
    cudaGetSymbolAddress((void**)&pWih1, g_Wih1);
    cudaGetSymbolAddress((void**)&pWhh1, g_Whh1);
    cudaGetSymbolAddress((void**)&pW0p,  g_W0p);
    cudaGetSymbolAddress((void**)&pA0,   g_A0);
    cudaGetSymbolAddress((void**)&pH0s,  g_h0s);
    cudaGetSymbolAddress((void**)&pHh,   g_hh);
    cudaGetSymbolAddress((void**)&pZh,   g_zh);
    cudaGetSymbolAddress((void**)&pGi0,  g_gi0);
    cudaGetSymbolAddress((void**)&pGi1,  g_gi1);
    cudaGetSymbolAddress((void**)&pGh,   g_gh);
    cudaGetSymbolAddress((void**)&pH,    g_h);
    cudaGetSymbolAddress((void**)&pZf,   g_zf);

    // zero h0 state buffers (defensive; also deterministic every call)
    zero_k<<<1600, 256>>>(pZf, pZh);

    // one-time (per replay) fp32 -> fp16 weight conversion
    const int n4 = (G3 * HH) / 4;
    f2h_k<<<4096, 256>>>(Whh0, pWhh0, n4);
    f2h_k<<<4096, 256>>>(Wih1, pWih1, n4);
    f2h_k<<<4096, 256>>>(Whh1, pWhh1, n4);
    prep_a0_k<<<(768 * IN0P + 255) / 256, 256>>>(x, pA0);
    prep_w0_k<<<(G3 * IN0P + 255) / 256, 256>>>(Wih0, pW0p);

    // gi0 = x0 @ W_ih0^T + b_ih0   (768 x 19200, K=256)
    gemm_f16<<<dim3(G3 / 128, 12), 256>>>(pA0, pW0p, bih0, pGi0, 768, G3, IN0P);

    // layer 0 recurrence
    for (int t = 0; t < TT; t++) {
        const __half* Ah = (t == 0) ? pZh : (pH0s + (size_t)(t - 1) * BH);
        gemm_f16<<<dim3(G3 / 128, 1), 256>>>(Ah, pWhh0, bhh0, pGh, 64, G3, HH);
        const float* hp = (t == 0) ? pZf : pH;
        float* extra = (t == TT - 1) ? (out + TBH) : nullptr;  // hidden[0]
        gate_k<<<1600, 256>>>(pGi0 + (size_t)t * 64 * G3, pGh, hp,
                              pH, pH0s + (size_t)t * BH, extra);
    }

    // gi1 = h0_states @ W_ih1^T + b_ih1   (768 x 19200, K=6400)
    gemm_f16<<<dim3(G3 / 128, 12), 256>>>(pH0s, pWih1, bih1, pGi1, 768, G3, HH);

    // layer 1 recurrence (writes output states directly into d_out)
    for (int t = 0; t < TT; t++) {
        const __half* Ah = (t == 0) ? pZh : pHh;
        gemm_f16<<<dim3(G3 / 128, 1), 256>>>(Ah, pWhh1, bhh1, pGh, 64, G3, HH);
        const float* hp = (t == 0) ? pZf : (out + (size_t)(t - 1) * BH);
        float* extra = (t == TT - 1) ? (out + TBH + BH) : nullptr;  // hidden[1]
        gate_k<<<1600, 256>>>(pGi1 + (size_t)t * 64 * G3, pGh, hp,
                              out + (size_t)t * BH, pHh, extra);
    }
}

// round 5
// speedup vs baseline: 2.0753x; 2.0753x over previous
#include <cuda_runtime.h>
#include <cuda_fp16.h>
#include <cstdint>
#include <cstddef>

// Problem constants
#define BB   64
#define TT   12
#define HH   6400
#define G3   19200            // 3*H
#define IN0P 256              // layer-0 input size padded 200 -> 256
#define BH   (BB*HH)          // 409600
#define TBH  (TT*BB*HH)       // 4915200

// ---------------- device scratch (sanctioned: __device__ globals) -------------
__device__ __half g_Whh0[(size_t)G3*HH];
__device__ __half g_Wih1[(size_t)G3*HH];
__device__ __half g_Whh1[(size_t)G3*HH];
__device__ __half g_W0p [(size_t)G3*IN0P];
__device__ __half g_A0  [768*IN0P];
__device__ float  g_gi0 [(size_t)768*G3];
__device__ float  g_gi1 [(size_t)768*G3];
__device__ __half g_h0s [TBH];
__device__ float  g_gh  [(size_t)BB*G3];
__device__ float  g_h   [BH];
__device__ __half g_hh  [BH];
__device__ float  g_zf  [BH];
__device__ __half g_zh  [BH];

// ---------------- fp32 -> fp16 bulk convert -----------------------------------
__global__ void f2h_k(const float* __restrict__ s, __half* __restrict__ d, int n4)
{
    int i = blockIdx.x * blockDim.x + threadIdx.x;
    int str = gridDim.x * blockDim.x;
    for (; i < n4; i += str) {
        float4 v = ((const float4*)s)[i];
        __half2 h0 = __floats2half2_rn(v.x, v.y);
        __half2 h1 = __floats2half2_rn(v.z, v.w);
        uint2 o;
        o.x = *(uint32_t*)&h0;
        o.y = *(uint32_t*)&h1;
        ((uint2*)d)[i] = o;
    }
}

// layer-0 A: (B,T,200) -> padded (T*B, 256) fp16, row = t*64+b
__global__ void prep_a0_k(const float* __restrict__ x, __half* __restrict__ d)
{
    int idx = blockIdx.x * 256 + threadIdx.x;
    if (idx >= 768 * IN0P) return;
    int row = idx >> 8, c = idx & 255;
    int t = row >> 6, b = row & 63;
    float v = (c < 200) ? x[b * 2400 + t * 200 + c] : 0.f;
    d[idx] = __float2half_rn(v);
}

// W_ih0: (19200,200) -> padded (19200,256) fp16
__global__ void prep_w0_k(const float* __restrict__ w, __half* __restrict__ d)
{
    int idx = blockIdx.x * 256 + threadIdx.x;
    if (idx >= G3 * IN0P) return;
    int g = idx >> 8, c = idx & 255;
    float v = (c < 200) ? w[g * 200 + c] : 0.f;
    d[idx] = __float2half_rn(v);
}

__global__ void zero_k(float* zf, __half* zh)
{
    int idx = blockIdx.x * 256 + threadIdx.x;
    if (idx < BH) { zf[idx] = 0.f; zh[idx] = __float2half(0.f); }
}

// ---------------- pipelined fp16 tensor-core GEMM: C = A * W^T + bias ---------
// A: (M,K) fp16 rm, W: (N,K) fp16 rm, C: (M,N) fp32.
// CTA tile: (MT*64) x 128, 8 warps as 2(M) x 4(N). K-chunk = 64 halfs (128B rows).
// Both A and W staged through smem via cp.async, S-stage pipeline, XOR-swizzled
// 128B rows (conflict-free ldmatrix). grid: x = M-blocks, y = N-blocks (m-major
// bid order -> same-N CTAs coresident -> W strips hit L2 on the big GEMMs).
__device__ __forceinline__ void cpa16(uint32_t d, const void* s)
{
    asm volatile("cp.async.cg.shared.global [%0], [%1], 16;\n" :: "r"(d), "l"(s));
}

template<int MT, int S>
__global__ void __launch_bounds__(256) gemm_pipe(
    const __half* __restrict__ A, const __half* __restrict__ W,
    const float* __restrict__ bias, float* __restrict__ C,
    int N, int K)
{
    extern __shared__ char sm[];
    constexpr int AB = MT * 64 * 128;   // A stage bytes
    constexpr int WB = 128 * 128;       // W stage bytes
    constexpr int SB = AB + WB;         // stage stride

    const int tid  = threadIdx.x;
    const int warp = tid >> 5;
    const int lane = tid & 31;
    const int warpM = warp >> 2;        // 0..1
    const int warpN = warp & 3;         // 0..3
    const int mbase = blockIdx.x * (MT * 64);
    const int nbase = blockIdx.y * 128;
    const __half* Ab = A + (size_t)mbase * K;
    const __half* Wb = W + (size_t)nbase * K;
    const int nk = K >> 6;

    float acc[2 * MT][4][4];
#pragma unroll
    for (int a = 0; a < 2 * MT; a++)
#pragma unroll
        for (int b = 0; b < 4; b++)
#pragma unroll
            for (int c = 0; c < 4; c++) acc[a][b][c] = 0.f;

    auto issue = [&](int slot, int it) {
        char* dA = sm + slot * SB;
        char* dW = dA + AB;
        const int kk = it << 6;
#pragma unroll
        for (int i = 0; i < 4; i++) {                 // W: 128 rows x 8 chunks
            int cid = tid + 256 * i;
            int row = cid >> 3, c = cid & 7;
            cpa16((uint32_t)__cvta_generic_to_shared(
                      dW + row * 128 + ((c ^ (row & 7)) << 4)),
                  Wb + (size_t)row * K + kk + c * 8);
        }
#pragma unroll
        for (int i = 0; i < 2 * MT; i++) {            // A: MT*64 rows x 8 chunks
            int cid = tid + 256 * i;
            int row = cid >> 3, c = cid & 7;
            cpa16((uint32_t)__cvta_generic_to_shared(
                      dA + row * 128 + ((c ^ (row & 7)) << 4)),
                  Ab + (size_t)row * K + kk + c * 8);
        }
    };

#pragma unroll
    for (int s = 0; s < S - 1; s++) {
        if (s < nk) issue(s, s);
        asm volatile("cp.async.commit_group;\n" ::);
    }

    int wslot = (S - 1) % S;
    int rslot = 0;
    for (int it = 0; it < nk; ++it) {
        int pre = it + (S - 1);
        if (pre < nk) issue(wslot, pre);
        asm volatile("cp.async.commit_group;\n" ::);
        wslot = (wslot + 1 == S) ? 0 : wslot + 1;

        asm volatile("cp.async.wait_group %0;\n" :: "n"(S - 1));
        __syncthreads();

        const char* stA = sm + rslot * SB;
        const char* stW = stA + AB;

#pragma unroll
        for (int ks = 0; ks < 4; ks++) {
            // W fragments: this warp's 32 N-cols = 4 n8-tiles, two x4 ldmatrix
            uint32_t bw[4][2];
#pragma unroll
            for (int h = 0; h < 2; h++) {
                int row = warpN * 32 + h * 16 + (lane & 7) + ((lane >> 4) << 3);
                int c = 2 * ks + ((lane >> 3) & 1);
                uint32_t ad = (uint32_t)__cvta_generic_to_shared(
                    stW + row * 128 + ((c ^ (row & 7)) << 4));
                asm volatile(
                    "ldmatrix.sync.aligned.m8n8.x4.shared.b16 {%0,%1,%2,%3}, [%4];\n"
                    : "=r"(bw[2*h][0]), "=r"(bw[2*h][1]),
                      "=r"(bw[2*h+1][0]), "=r"(bw[2*h+1][1])
                    : "r"(ad));
            }
#pragma unroll
            for (int mtl = 0; mtl < 2 * MT; mtl++) {
                int row = (warpM * 2 * MT + mtl) * 16 + (lane & 15);
                int c = 2 * ks + (lane >> 4);
                uint32_t ad = (uint32_t)__cvta_generic_to_shared(
                    stA + row * 128 + ((c ^ (row & 7)) << 4));
                uint32_t a0, a1, a2, a3;
                asm volatile(
                    "ldmatrix.sync.aligned.m8n8.x4.shared.b16 {%0,%1,%2,%3}, [%4];\n"
                    : "=r"(a0), "=r"(a1), "=r"(a2), "=r"(a3) : "r"(ad));
#pragma unroll
                for (int nt = 0; nt < 4; nt++) {
                    asm volatile(
                        "mma.sync.aligned.m16n8k16.row.col.f32.f16.f16.f32 "
                        "{%0,%1,%2,%3}, {%4,%5,%6,%7}, {%8,%9}, {%0,%1,%2,%3};\n"
                        : "+f"(acc[mtl][nt][0]), "+f"(acc[mtl][nt][1]),
                          "+f"(acc[mtl][nt][2]), "+f"(acc[mtl][nt][3])
                        : "r"(a0), "r"(a1), "r"(a2), "r"(a3),
                          "r"(bw[nt][0]), "r"(bw[nt][1]));
                }
            }
        }
        __syncthreads();
        rslot = (rslot + 1 == S) ? 0 : rslot + 1;
    }

    // epilogue: C[m][n] = acc + bias[n]
#pragma unroll
    for (int mtl = 0; mtl < 2 * MT; mtl++) {
        int row = mbase + (warpM * 2 * MT + mtl) * 16 + (lane >> 2);
#pragma unroll
        for (int nt = 0; nt < 4; nt++) {
            int col = nbase + warpN * 32 + nt * 8 + (lane & 3) * 2;
            float bv0 = bias[col], bv1 = bias[col + 1];
            float2 v0 = make_float2(acc[mtl][nt][0] + bv0, acc[mtl][nt][1] + bv1);
            float2 v1 = make_float2(acc[mtl][nt][2] + bv0, acc[mtl][nt][3] + bv1);
            *(float2*)&C[(size_t)row * N + col]       = v0;
            *(float2*)&C[(size_t)(row + 8) * N + col] = v1;
        }
    }
}

// ---------------- fused GRU gate pointwise ------------------------------------
__global__ void gate_k(const float* __restrict__ gi, const float* __restrict__ gh,
                       const float* __restrict__ hp, float* __restrict__ ho,
                       __half* __restrict__ hoh, float* __restrict__ extra)
{
    int idx = blockIdx.x * 256 + threadIdx.x;
    if (idx >= BH) return;
    int b = idx / HH, j = idx - b * HH;
    const float* gib = gi + (size_t)b * G3;
    const float* ghb = gh + (size_t)b * G3;
    float xr = gib[j]          + ghb[j];
    float xz = gib[j + HH]     + ghb[j + HH];
    float r  = 1.f / (1.f + __expf(-xr));
    float z  = 1.f / (1.f + __expf(-xz));
    float n  = tanhf(gib[j + 2 * HH] + r * ghb[j + 2 * HH]);
    float hn = fmaf(z, hp[idx] - n, n);
    ho[idx]  = hn;
    hoh[idx] = __float2half_rn(hn);
    if (extra) extra[idx] = hn;
}

// ---------------- host orchestration ------------------------------------------
extern "C" void kernel_launch(void* const* d_in, const int* in_sizes, int n_in,
                              void* d_out, int out_size)
{
    const float* x    = (const float*)d_in[0];
    const float* Wih0 = (const float*)d_in[1];
    const float* Whh0 = (const float*)d_in[2];
    const float* bih0 = (const float*)d_in[3];
    const float* bhh0 = (const float*)d_in[4];
    const float* Wih1 = (const float*)d_in[5];
    const float* Whh1 = (const float*)d_in[6];
    const float* bih1 = (const float*)d_in[7];
    const float* bhh1 = (const float*)d_in[8];
    float* out = (float*)d_out;

    __half *pWhh0, *pWih1, *pWhh1, *pW0p, *pA0, *pH0s, *pHh, *pZh;
    float  *pGi0, *pGi1, *pGh, *pH, *pZf;
    cudaGetSymbolAddress((void**)&pWhh0, g_Whh0);
    cudaGetSymbolAddress((void**)&pWih1, g_Wih1);
    cudaGetSymbolAddress((void**)&pWhh1, g_Whh1);
    cudaGetSymbolAddress((void**)&pW0p,  g_W0p);
    cudaGetSymbolAddress((void**)&pA0,   g_A0);
    cudaGetSymbolAddress((void**)&pH0s,  g_h0s);
    cudaGetSymbolAddress((void**)&pHh,   g_hh);
    cudaGetSymbolAddress((void**)&pZh,   g_zh);
    cudaGetSymbolAddress((void**)&pGi0,  g_gi0);
    cudaGetSymbolAddress((void**)&pGi1,  g_gi1);
    cudaGetSymbolAddress((void**)&pGh,   g_gh);
    cudaGetSymbolAddress((void**)&pH,    g_h);
    cudaGetSymbolAddress((void**)&pZf,   g_zf);

    // opt-in to 96KB dynamic smem (host-side attribute set; not a stream op)
    const int SMEM = 98304;
    cudaFuncSetAttribute(gemm_pipe<1,4>, cudaFuncAttributeMaxDynamicSharedMemorySize, SMEM);
    cudaFuncSetAttribute(gemm_pipe<2,3>, cudaFuncAttributeMaxDynamicSharedMemorySize, SMEM);

    zero_k<<<1600, 256>>>(pZf, pZh);

    const int n4 = (G3 * HH) / 4;
    f2h_k<<<4096, 256>>>(Whh0, pWhh0, n4);
    f2h_k<<<4096, 256>>>(Wih1, pWih1, n4);
    f2h_k<<<4096, 256>>>(Whh1, pWhh1, n4);
    prep_a0_k<<<(768 * IN0P + 255) / 256, 256>>>(x, pA0);
    prep_w0_k<<<(G3 * IN0P + 255) / 256, 256>>>(Wih0, pW0p);

    // gi0 = x0 @ W_ih0^T + b_ih0   (768 x 19200, K=256)  tile 128x128
    gemm_pipe<2,3><<<dim3(6, G3 / 128), 256, SMEM>>>(pA0, pW0p, bih0, pGi0, G3, IN0P);

    // layer 0 recurrence (tile 64x128, 4-stage pipeline)
    for (int t = 0; t < TT; t++) {
        const __half* Ah = (t == 0) ? pZh : (pH0s + (size_t)(t - 1) * BH);
        gemm_pipe<1,4><<<dim3(1, G3 / 128), 256, SMEM>>>(Ah, pWhh0, bhh0, pGh, G3, HH);
        const float* hp = (t == 0) ? pZf : pH;
        float* extra = (t == TT - 1) ? (out + TBH) : nullptr;  // hidden[0]
        gate_k<<<1600, 256>>>(pGi0 + (size_t)t * 64 * G3, pGh, hp,
                              pH, pH0s + (size_t)t * BH, extra);
    }

    // gi1 = h0_states @ W_ih1^T + b_ih1   (768 x 19200, K=6400)  tile 128x128
    gemm_pipe<2,3><<<dim3(6, G3 / 128), 256, SMEM>>>(pH0s, pWih1, bih1, pGi1, G3, HH);

    // layer 1 recurrence (writes output states directly into d_out)
    for (int t = 0; t < TT; t++) {
        const __half* Ah = (t == 0) ? pZh : pHh;
        gemm_pipe<1,4><<<dim3(1, G3 / 128), 256, SMEM>>>(Ah, pWhh1, bhh1, pGh, G3, HH);
        const float* hp = (t == 0) ? pZf : (out + (size_t)(t - 1) * BH);
        float* extra = (t == TT - 1) ? (out + TBH + BH) : nullptr;  // hidden[1]
        gate_k<<<1600, 256>>>(pGi1 + (size_t)t * 64 * G3, pGh, hp,
                              out + (size_t)t * BH, pHh, extra);
    }
}